// round 4
// baseline (speedup 1.0000x reference)
#include <cuda_runtime.h>

// RFCM loss — single fused kernel, v3.
// y_pred: [2,4,128,128,128] f32 (softmax), image: [2,1,128,128,128] f32 -> scalar f32.
// J1 = (1/N)*sum_{b,k}(C - A^2/B); A=sum(mem*img), B=sum(mem), C=sum(mem*img^2)
// J2 voxel = M*(S27-M) - sum_k mem_k*(s27_k-mem_k);  mem = y_pred^2, zero-pad stencil.

#define FULLMASK 0xffffffffu

__device__ double g_acc[25];
__device__ unsigned int g_sem;

__device__ __forceinline__ float4 sq4(float4 p) {
    float4 m; m.x = p.x*p.x; m.y = p.y*p.y; m.z = p.z*p.z; m.w = p.w*p.w; return m;
}
__device__ __forceinline__ float4 add4(float4 a, float4 b) {
    float4 r; r.x=a.x+b.x; r.y=a.y+b.y; r.z=a.z+b.z; r.w=a.w+b.w; return r;
}

__global__ __launch_bounds__(256, 3)
void rfcm_kernel(const float* __restrict__ ypred, const float* __restrict__ image,
                 float* __restrict__ out) {
    // Double-buffered x-3-sum planes: [slot][k][yrow(10, halo)][32 float4]
    __shared__ float4 s_xs[2][4][10][32];
    __shared__ float  s_red[8 * 13];

    const int tx  = threadIdx.x;          // x chunk of 4
    const int ty  = threadIdx.y;          // owned y row / warp id (0..7)
    const int tid = ty * 32 + tx;
    const int y0  = blockIdx.x * 8;
    const int z0  = blockIdx.y * 8;
    const int b   = blockIdx.z;

    const float* yp_b = ypred + (size_t)b * 4 * 128 * 16384;
    const float* im_b = image + (size_t)b * 128 * 16384;

    float4 qA[4], qB[4], qC[4];
    float accB[4] = {0,0,0,0}, accA[4] = {0,0,0,0}, accC[4] = {0,0,0,0};
    float4 j2 = make_float4(0.f, 0.f, 0.f, 0.f);

    auto xsum = [&](float4 m) -> float4 {
        float lf = __shfl_up_sync(FULLMASK, m.w, 1);
        float rt = __shfl_down_sync(FULLMASK, m.x, 1);
        if (tx == 0)  lf = 0.f;
        if (tx == 31) rt = 0.f;
        float4 r;
        r.x = lf  + m.x + m.y;
        r.y = m.x + m.y + m.z;
        r.z = m.y + m.z + m.w;
        r.w = m.z + m.w + rt;
        return r;
    };

    // Build 2D 9-sum plane at depth zz into q[]; cooperative row loading.
    auto plane = [&](int zz, float4 (&q)[4]) {
        if ((unsigned)zz >= 128u) {
            #pragma unroll
            for (int k = 0; k < 4; k++) q[k] = make_float4(0.f, 0.f, 0.f, 0.f);
            return;
        }
        const int slot = (zz + 1 - z0) & 1;
        // 40 (k,yrow) rows distributed over 8 warps, 5 each.
        #pragma unroll
        for (int i = 0; i < 5; i++) {
            const int ri = ty + 8 * i;
            const int k  = ri / 10;
            const int yr = ri - k * 10;
            const int gy = y0 - 1 + yr;
            float4 p = make_float4(0.f, 0.f, 0.f, 0.f);
            if ((unsigned)gy < 128u)
                p = *(const float4*)(yp_b + (((size_t)(k * 128 + zz)) << 14) + (gy << 7) + (tx << 2));
            s_xs[slot][k][yr][tx] = xsum(sq4(p));
        }
        __syncthreads();
        #pragma unroll
        for (int k = 0; k < 4; k++)
            q[k] = add4(add4(s_xs[slot][k][ty][tx], s_xs[slot][k][ty + 1][tx]),
                        s_xs[slot][k][ty + 2][tx]);
    };

    plane(z0 - 1, qA);
    plane(z0,     qB);

    const int gy = y0 + ty;
    for (int zi = 0; zi < 8; zi++) {
        const int z = z0 + zi;
        plane(z + 1, qC);

        const float4 img = *(const float4*)(im_b + (((size_t)z) << 14) + (gy << 7) + (tx << 2));
        const float4 i2 = sq4(img);
        float4 M = make_float4(0.f,0.f,0.f,0.f);
        float4 S = make_float4(0.f,0.f,0.f,0.f);
        float4 X = make_float4(0.f,0.f,0.f,0.f);
        #pragma unroll
        for (int k = 0; k < 4; k++) {
            // Center mem reloaded from gmem (L1-hot: fetched during plane(z) build).
            float4 mc = sq4(*(const float4*)(yp_b + (((size_t)(k * 128 + z)) << 14) + (gy << 7) + (tx << 2)));
            float4 s27 = add4(add4(qA[k], qB[k]), qC[k]);
            accB[k] += (mc.x + mc.y) + (mc.z + mc.w);
            accA[k] += fmaf(mc.x, img.x, fmaf(mc.y, img.y, fmaf(mc.z, img.z, mc.w * img.w)));
            accC[k] += fmaf(mc.x, i2.x,  fmaf(mc.y, i2.y,  fmaf(mc.z, i2.z,  mc.w * i2.w)));
            M = add4(M, mc);
            S = add4(S, s27);
            X.x = fmaf(mc.x, s27.x - mc.x, X.x);
            X.y = fmaf(mc.y, s27.y - mc.y, X.y);
            X.z = fmaf(mc.z, s27.z - mc.z, X.z);
            X.w = fmaf(mc.w, s27.w - mc.w, X.w);
        }
        j2.x += fmaf(M.x, S.x - M.x, -X.x);
        j2.y += fmaf(M.y, S.y - M.y, -X.y);
        j2.z += fmaf(M.z, S.z - M.z, -X.z);
        j2.w += fmaf(M.w, S.w - M.w, -X.w);

        #pragma unroll
        for (int k = 0; k < 4; k++) { qA[k] = qB[k]; qB[k] = qC[k]; }
    }

    // ---- block reduction ----
    float vals[13];
    #pragma unroll
    for (int k = 0; k < 4; k++) { vals[k] = accB[k]; vals[4 + k] = accA[k]; vals[8 + k] = accC[k]; }
    vals[12] = (j2.x + j2.y) + (j2.z + j2.w);

    #pragma unroll
    for (int q = 0; q < 13; q++) {
        float v = vals[q];
        #pragma unroll
        for (int off = 16; off; off >>= 1) v += __shfl_xor_sync(FULLMASK, v, off);
        vals[q] = v;
    }
    __syncthreads();   // reuse of s_red region is fresh; also orders prior smem use
    if (tx == 0) {
        #pragma unroll
        for (int q = 0; q < 13; q++) s_red[ty * 13 + q] = vals[q];
    }
    __syncthreads();
    if (tid < 13) {
        float s = 0.f;
        #pragma unroll
        for (int w = 0; w < 8; w++) s += s_red[w * 13 + tid];
        double* dst;
        if (tid < 4)       dst = &g_acc[b * 4 + tid];
        else if (tid < 8)  dst = &g_acc[8 + b * 4 + (tid - 4)];
        else if (tid < 12) dst = &g_acc[16 + b * 4 + (tid - 8)];
        else               dst = &g_acc[24];
        atomicAdd(dst, (double)s);
        __threadfence();
    }
    __syncthreads();

    // ---- last block (of 512) finalizes and resets for the next graph replay ----
    if (tid == 0) {
        unsigned old = atomicAdd(&g_sem, 1u);
        if (old == 511u) {
            volatile double* ga = g_acc;
            double j1 = 0.0;
            #pragma unroll
            for (int i = 0; i < 8; i++) {
                double Bv = ga[i], Av = ga[8 + i], Cv = ga[16 + i];
                j1 += Cv - Av * Av / Bv;
            }
            const double inv = 1.0 / 4194304.0;
            out[0] = (float)(j1 * inv + 0.0008 * ga[24] * inv);
            #pragma unroll
            for (int i = 0; i < 25; i++) g_acc[i] = 0.0;
            g_sem = 0u;
        }
    }
}

extern "C" void kernel_launch(void* const* d_in, const int* in_sizes, int n_in,
                              void* d_out, int out_size) {
    const float* ypred = (const float*)d_in[0];
    const float* image = (const float*)d_in[1];
    if (n_in >= 2 && in_sizes[0] < in_sizes[1]) {  // robustness to input order
        ypred = (const float*)d_in[1];
        image = (const float*)d_in[0];
    }
    rfcm_kernel<<<dim3(16, 16, 2), dim3(32, 8)>>>(ypred, image, (float*)d_out);
}

// round 5
// speedup vs baseline: 1.5228x; 1.5228x over previous
#include <cuda_runtime.h>

// RFCM loss — fused single kernel, v4: z-sum-first separable stencil,
// k-channels split across threadIdx.z to halve register state -> 32 warps/SM.
// y_pred: [2,4,128,128,128] f32 (softmax), image: [2,1,128,128,128] f32 -> scalar.
// J1 = (1/N)*sum_{b,k}(C - A^2/B);  J2 voxel = M*(S27-M) - sum_k mem_k*(s27_k-mem_k)

#define FULLMASK 0xffffffffu

__device__ double g_acc[25];
__device__ unsigned int g_sem;

__device__ __forceinline__ float4 sq4(float4 p) {
    float4 m; m.x=p.x*p.x; m.y=p.y*p.y; m.z=p.z*p.z; m.w=p.w*p.w; return m;
}
__device__ __forceinline__ float4 add4(float4 a, float4 b) {
    float4 r; r.x=a.x+b.x; r.y=a.y+b.y; r.z=a.z+b.z; r.w=a.w+b.w; return r;
}

// shared carve (float4 units): s_xs [4][18][32], s_ex [2][16][32], s_red floats
#define XS_F4  (4*18*32)
#define EX_F4  (2*16*32)
#define SMEM_BYTES ((XS_F4 + EX_F4) * 16 + 32*8*4)

__global__ __launch_bounds__(1024, 1)
void rfcm_kernel(const float* __restrict__ ypred, const float* __restrict__ image,
                 float* __restrict__ out) {
    extern __shared__ float4 smem4[];
    float4* s_xs = smem4;            // [k][yr 0..17][tx]
    float4* s_ex = smem4 + XS_F4;    // [0]=M1 [1]=S1, [ty][tx]
    float*  s_red = (float*)(smem4 + XS_F4 + EX_F4);

    const int tx = threadIdx.x;              // x quad
    const int ty = threadIdx.y;              // y row 0..15
    const int tk = threadIdx.z;              // k group 0..1
    const int tid = tx + 32*ty + 512*tk;
    const int wid = ty + 16*tk;
    const int y0 = blockIdx.x * 16;
    const int z0 = blockIdx.y * 8;
    const int b  = blockIdx.z;
    const int gy = y0 + ty;

    const float* yp_b = ypred + (size_t)b * 4 * 128 * 16384;
    const float* im_b = image + (size_t)b * 128 * 16384;

    auto ldsq = [&](int k, int zz, int yy) -> float4 {
        float4 p = make_float4(0.f,0.f,0.f,0.f);
        if ((unsigned)zz < 128u && (unsigned)yy < 128u)
            p = *(const float4*)(yp_b + (((size_t)(k*128+zz))<<14) + (yy<<7) + (tx<<2));
        return sq4(p);
    };
    auto xsum = [&](float4 m) -> float4 {
        float lf = __shfl_up_sync(FULLMASK, m.w, 1);
        float rt = __shfl_down_sync(FULLMASK, m.x, 1);
        if (tx == 0)  lf = 0.f;
        if (tx == 31) rt = 0.f;
        float4 r;
        r.x = lf  + m.x + m.y;
        r.y = m.x + m.y + m.z;
        r.z = m.y + m.z + m.w;
        r.w = m.z + m.w + rt;
        return r;
    };

    // raw mem z-window for own row, 2 k's per group
    float4 m0[2], m1[2], m2[2];
    #pragma unroll
    for (int j = 0; j < 2; j++) {
        const int k = 2*tk + j;
        m0[j] = ldsq(k, z0 - 1, gy);
        m1[j] = ldsq(k, z0,     gy);
    }

    float accB[2] = {0,0}, accA[2] = {0,0}, accC[2] = {0,0};
    float4 j2v = make_float4(0.f,0.f,0.f,0.f);

    for (int zi = 0; zi < 8; zi++) {
        const int z = z0 + zi;
        // build x-sum-of-z-sum plane
        #pragma unroll
        for (int j = 0; j < 2; j++) {
            const int k = 2*tk + j;
            m2[j] = ldsq(k, z + 1, gy);
            float4 zs = add4(add4(m0[j], m1[j]), m2[j]);
            s_xs[(k*18 + ty + 1)*32 + tx] = xsum(zs);
        }
        if (ty == 0) {           // y0-1 halo row (stateless, L1-hot)
            #pragma unroll
            for (int j = 0; j < 2; j++) {
                const int k = 2*tk + j;
                float4 zh = add4(add4(ldsq(k, z-1, y0-1), ldsq(k, z, y0-1)), ldsq(k, z+1, y0-1));
                s_xs[(k*18 + 0)*32 + tx] = xsum(zh);
            }
        } else if (ty == 15) {   // y0+16 halo row
            #pragma unroll
            for (int j = 0; j < 2; j++) {
                const int k = 2*tk + j;
                float4 zh = add4(add4(ldsq(k, z-1, y0+16), ldsq(k, z, y0+16)), ldsq(k, z+1, y0+16));
                s_xs[(k*18 + 17)*32 + tx] = xsum(zh);
            }
        }
        __syncthreads();

        const float4 img = *(const float4*)(im_b + (((size_t)z)<<14) + (gy<<7) + (tx<<2));
        float4 Mg = make_float4(0.f,0.f,0.f,0.f);
        float4 Sg = make_float4(0.f,0.f,0.f,0.f);
        #pragma unroll
        for (int j = 0; j < 2; j++) {
            const int k = 2*tk + j;
            float4 s27 = add4(add4(s_xs[(k*18 + ty)*32 + tx],
                                   s_xs[(k*18 + ty + 1)*32 + tx]),
                              s_xs[(k*18 + ty + 2)*32 + tx]);
            const float4 mc = m1[j];   // center mem, free from the window
            accB[j] += (mc.x + mc.y) + (mc.z + mc.w);
            float tX = mc.x*img.x, tY = mc.y*img.y, tZ = mc.z*img.z, tW = mc.w*img.w;
            accA[j] += (tX + tY) + (tZ + tW);
            accC[j] += fmaf(tX, img.x, fmaf(tY, img.y, fmaf(tZ, img.z, tW*img.w)));
            Mg = add4(Mg, mc);
            Sg = add4(Sg, s27);
            j2v.x = fmaf(mc.x, mc.x - s27.x, j2v.x);   // -= mc*(s27-mc)
            j2v.y = fmaf(mc.y, mc.y - s27.y, j2v.y);
            j2v.z = fmaf(mc.z, mc.z - s27.z, j2v.z);
            j2v.w = fmaf(mc.w, mc.w - s27.w, j2v.w);
        }
        if (tk == 1) {
            s_ex[(0*16 + ty)*32 + tx] = Mg;
            s_ex[(1*16 + ty)*32 + tx] = Sg;
        }
        __syncthreads();
        if (tk == 0) {
            float4 Mo = s_ex[(0*16 + ty)*32 + tx];
            float4 So = s_ex[(1*16 + ty)*32 + tx];
            float4 M = add4(Mg, Mo), S = add4(Sg, So);
            j2v.x = fmaf(M.x, S.x - M.x, j2v.x);
            j2v.y = fmaf(M.y, S.y - M.y, j2v.y);
            j2v.z = fmaf(M.z, S.z - M.z, j2v.z);
            j2v.w = fmaf(M.w, S.w - M.w, j2v.w);
        }
        #pragma unroll
        for (int j = 0; j < 2; j++) { m0[j] = m1[j]; m1[j] = m2[j]; }
    }

    // ---- reduction: 7 quantities per group ----
    float vals[7] = { accB[0], accB[1], accA[0], accA[1], accC[0], accC[1],
                      (j2v.x + j2v.y) + (j2v.z + j2v.w) };
    #pragma unroll
    for (int q = 0; q < 7; q++) {
        float v = vals[q];
        #pragma unroll
        for (int off = 16; off; off >>= 1) v += __shfl_xor_sync(FULLMASK, v, off);
        vals[q] = v;
    }
    if (tx == 0) {
        #pragma unroll
        for (int q = 0; q < 7; q++) s_red[wid*8 + q] = vals[q];
    }
    __syncthreads();
    if (tid < 14) {
        const int g = tid / 7, q = tid % 7;
        float s = 0.f;
        #pragma unroll
        for (int w = 0; w < 16; w++) s += s_red[(16*g + w)*8 + q];
        double* dst;
        if (q < 2)       dst = &g_acc[b*4 + 2*g + q];
        else if (q < 4)  dst = &g_acc[8 + b*4 + 2*g + (q - 2)];
        else if (q < 6)  dst = &g_acc[16 + b*4 + 2*g + (q - 4)];
        else             dst = &g_acc[24];
        atomicAdd(dst, (double)s);
        __threadfence();
    }
    __syncthreads();

    // ---- last of 256 blocks finalizes, resets for next graph replay ----
    if (tid == 0) {
        unsigned old = atomicAdd(&g_sem, 1u);
        if (old == 255u) {
            volatile double* ga = g_acc;
            double j1 = 0.0;
            #pragma unroll
            for (int i = 0; i < 8; i++) {
                double Bv = ga[i], Av = ga[8 + i], Cv = ga[16 + i];
                j1 += Cv - Av * Av / Bv;
            }
            const double inv = 1.0 / 4194304.0;
            out[0] = (float)(j1 * inv + 0.0008 * ga[24] * inv);
            #pragma unroll
            for (int i = 0; i < 25; i++) g_acc[i] = 0.0;
            g_sem = 0u;
        }
    }
}

extern "C" void kernel_launch(void* const* d_in, const int* in_sizes, int n_in,
                              void* d_out, int out_size) {
    const float* ypred = (const float*)d_in[0];
    const float* image = (const float*)d_in[1];
    if (n_in >= 2 && in_sizes[0] < in_sizes[1]) {  // robustness to input order
        ypred = (const float*)d_in[1];
        image = (const float*)d_in[0];
    }
    cudaFuncSetAttribute(rfcm_kernel, cudaFuncAttributeMaxDynamicSharedMemorySize,
                         SMEM_BYTES);
    rfcm_kernel<<<dim3(8, 16, 2), dim3(32, 16, 2), SMEM_BYTES>>>(ypred, image, (float*)d_out);
}